// round 3
// baseline (speedup 1.0000x reference)
#include <cuda_runtime.h>
#include <math.h>

#define BN   8
#define NN   16384
#define DD   768
#define RR   3
#define NEXP 4
#define HH   128

// ---------------- scratch (device globals; no allocation allowed) ----------------
__device__ float g_xr[BN * RR * NN];     // feat layout: [(b*3+r)*16384 + n], n = y*128+x
__device__ float g_mx[BN * RR * NN];     // mixed, same layout
__device__ float g_part[16384 * 3];      // per-block partial sums for the mean
__device__ float g_G[BN * NEXP];         // gate weights
__device__ float g_db[BN * RR * 64 * 64];// downsampled feat (largest = 64x64)
__device__ float g_cb[BN * RR * 64 * 64];// conv output at downsampled res

// ---------------- pass 1: xr = x @ Wd + bd, + per-block partial sums -------------
__global__ void k_xr(const float* __restrict__ x, const float* __restrict__ Wd,
                     const float* __restrict__ bd)
{
    __shared__ float4 sW[3][192];     // Wd transposed: sW[r][e4]
    __shared__ float  sPart[8][3];
    int tid = threadIdx.x;
    float* sWf = (float*)sW;
    for (int i = tid; i < DD * RR; i += 256) {
        int r = i / DD, e = i % DD;
        sWf[r * DD + e] = Wd[e * RR + r];
    }
    __syncthreads();

    int warp = tid >> 5, lane = tid & 31;
    long long row = (long long)blockIdx.x * 8 + warp;   // (b*N + n)
    const float4* x4 = (const float4*)x + row * 192;

    float a0 = 0.f, a1 = 0.f, a2 = 0.f;
#pragma unroll
    for (int i = 0; i < 6; i++) {
        int j = i * 32 + lane;
        float4 xv = x4[j];
        float4 w0 = sW[0][j], w1 = sW[1][j], w2 = sW[2][j];
        a0 = fmaf(xv.x, w0.x, fmaf(xv.y, w0.y, fmaf(xv.z, w0.z, fmaf(xv.w, w0.w, a0))));
        a1 = fmaf(xv.x, w1.x, fmaf(xv.y, w1.y, fmaf(xv.z, w1.z, fmaf(xv.w, w1.w, a1))));
        a2 = fmaf(xv.x, w2.x, fmaf(xv.y, w2.y, fmaf(xv.z, w2.z, fmaf(xv.w, w2.w, a2))));
    }
#pragma unroll
    for (int o = 16; o; o >>= 1) {
        a0 += __shfl_down_sync(0xffffffffu, a0, o);
        a1 += __shfl_down_sync(0xffffffffu, a1, o);
        a2 += __shfl_down_sync(0xffffffffu, a2, o);
    }
    if (lane == 0) {
        int b = (int)(row >> 14);
        int n = (int)(row & 16383);
        a0 += bd[0]; a1 += bd[1]; a2 += bd[2];
        g_xr[(b * 3 + 0) * NN + n] = a0;
        g_xr[(b * 3 + 1) * NN + n] = a1;
        g_xr[(b * 3 + 2) * NN + n] = a2;
        sPart[warp][0] = a0; sPart[warp][1] = a1; sPart[warp][2] = a2;
    }
    __syncthreads();
    if (tid < 3) {
        float s = 0.f;
#pragma unroll
        for (int w = 0; w < 8; w++) s += sPart[w][tid];
        g_part[blockIdx.x * 3 + tid] = s;   // block's 8 rows all share one b
    }
}

// ---------------- pass 2: gating (deterministic reduction + top-2 softmax) -------
__global__ void k_gate(const float* __restrict__ noise, const float* __restrict__ Wg,
                       const float* __restrict__ Wn)
{
    __shared__ float xa[24];
    int tid = threadIdx.x;
    int warp = tid >> 5, lane = tid & 31;
    // 2048 blocks per batch in k_xr (16384 blocks total / 8 batches)
    for (int p = warp; p < 24; p += 8) {
        int b = p / 3, r = p % 3;
        float s = 0.f;
        for (int k = lane; k < 2048; k += 32)
            s += g_part[(b * 2048 + k) * 3 + r];
#pragma unroll
        for (int o = 16; o; o >>= 1) s += __shfl_down_sync(0xffffffffu, s, o);
        if (lane == 0) xa[p] = s * (1.0f / 16384.0f);
    }
    __syncthreads();
    if (tid < BN) {
        int b = tid;
        float v[NEXP];
#pragma unroll
        for (int e = 0; e < NEXP; e++) {
            float hg = 0.f, hn = 0.f;
#pragma unroll
            for (int r = 0; r < RR; r++) {
                hg = fmaf(xa[b * 3 + r], Wg[r * NEXP + e], hg);
                hn = fmaf(xa[b * 3 + r], Wn[r * NEXP + e], hn);
            }
            float sp = fmaxf(hn, 0.f) + log1pf(expf(-fabsf(hn)));  // stable softplus
            v[e] = hg + noise[b * NEXP + e] * sp;
        }
        int i1 = 0;
        for (int e = 1; e < NEXP; e++) if (v[e] > v[i1]) i1 = e;   // first-occurrence ties
        int i2 = -1;
        for (int e = 0; e < NEXP; e++) {
            if (e == i1) continue;
            if (i2 < 0 || v[e] > v[i2]) i2 = e;
        }
        // softmax over {v[i1], v[i2]}; masked entries (-1e30) underflow to exactly 0
        float e2 = expf(v[i2] - v[i1]);
        float inv = 1.0f / (1.0f + e2);
#pragma unroll
        for (int e = 0; e < NEXP; e++) g_G[b * NEXP + e] = 0.f;
        g_G[b * NEXP + i1] = inv;
        g_G[b * NEXP + i2] = e2 * inv;
    }
}

// ---------------- scale 1.0: dwconv at full res, write G0 * result into mixed ----
__global__ void k_conv1(const float* __restrict__ dwk, const float* __restrict__ dwb)
{
    int idx = blockIdx.x * blockDim.x + threadIdx.x;
    if (idx >= 24 * HH * HH) return;
    int p = idx >> 14;
    int rem = idx & 16383;
    int y = rem >> 7, xp = rem & 127;
    int r = p % 3, b = p / 3;
    const float* in = g_xr + p * NN;
    float acc = dwb[r];
#pragma unroll
    for (int dy = -1; dy <= 1; dy++) {
        int yy = y + dy;
        if (yy < 0 || yy >= HH) continue;
#pragma unroll
        for (int dx = -1; dx <= 1; dx++) {
            int xx = xp + dx;
            if (xx < 0 || xx >= HH) continue;
            acc = fmaf(in[yy * HH + xx], dwk[r * 9 + (dy + 1) * 3 + (dx + 1)], acc);
        }
    }
    g_mx[idx] = g_G[b * NEXP + 0] * acc;   // write mode (initializes g_mx)
}

// ---------------- half-pixel bilinear downsample 128 -> (oh, ow) -----------------
__global__ void k_down(int oh, int ow)
{
    int idx = blockIdx.x * blockDim.x + threadIdx.x;
    int plane = oh * ow;
    if (idx >= 24 * plane) return;
    int p = idx / plane;
    int rem = idx - p * plane;
    int y = rem / ow, xp = rem - y * ow;
    float sy = (y + 0.5f) * (128.0f / oh) - 0.5f;
    float sx = (xp + 0.5f) * (128.0f / ow) - 0.5f;
    int y0 = (int)floorf(sy); float fy = sy - y0;
    int x0 = (int)floorf(sx); float fx = sx - x0;
    int y0c = min(max(y0, 0), 127), y1c = min(max(y0 + 1, 0), 127);
    int x0c = min(max(x0, 0), 127), x1c = min(max(x0 + 1, 0), 127);
    const float* in = g_xr + p * NN;
    float v = (1.f - fy) * ((1.f - fx) * in[y0c * 128 + x0c] + fx * in[y0c * 128 + x1c])
            +        fy  * ((1.f - fx) * in[y1c * 128 + x0c] + fx * in[y1c * 128 + x1c]);
    g_db[idx] = v;
}

// ---------------- dwconv 3x3 (zero pad) at downsampled res -----------------------
__global__ void k_convs(const float* __restrict__ dwk, const float* __restrict__ dwb,
                        int h, int w)
{
    int idx = blockIdx.x * blockDim.x + threadIdx.x;
    int plane = h * w;
    if (idx >= 24 * plane) return;
    int p = idx / plane;
    int rem = idx - p * plane;
    int y = rem / w, xp = rem - y * w;
    int r = p % 3;
    const float* in = g_db + p * plane;
    float acc = dwb[r];
#pragma unroll
    for (int dy = -1; dy <= 1; dy++) {
        int yy = y + dy;
        if (yy < 0 || yy >= h) continue;
#pragma unroll
        for (int dx = -1; dx <= 1; dx++) {
            int xx = xp + dx;
            if (xx < 0 || xx >= w) continue;
            acc = fmaf(in[yy * w + xx], dwk[r * 9 + (dy + 1) * 3 + (dx + 1)], acc);
        }
    }
    g_cb[idx] = acc;
}

// ---------------- bilinear upsample (ih,iw) -> 128, accumulate G[b][j] * v -------
__global__ void k_up(int ih, int iw, int j)
{
    int idx = blockIdx.x * blockDim.x + threadIdx.x;
    if (idx >= 24 * HH * HH) return;
    int p = idx >> 14;
    int rem = idx & 16383;
    int y = rem >> 7, xp = rem & 127;
    float sy = (y + 0.5f) * (ih / 128.0f) - 0.5f;
    float sx = (xp + 0.5f) * (iw / 128.0f) - 0.5f;
    int y0 = (int)floorf(sy); float fy = sy - y0;
    int x0 = (int)floorf(sx); float fx = sx - x0;
    int y0c = min(max(y0, 0), ih - 1), y1c = min(max(y0 + 1, 0), ih - 1);
    int x0c = min(max(x0, 0), iw - 1), x1c = min(max(x0 + 1, 0), iw - 1);
    const float* in = g_cb + p * ih * iw;
    float v = (1.f - fy) * ((1.f - fx) * in[y0c * iw + x0c] + fx * in[y0c * iw + x1c])
            +        fy  * ((1.f - fx) * in[y1c * iw + x0c] + fx * in[y1c * iw + x1c]);
    int b = p / 3;
    g_mx[idx] += g_G[b * NEXP + j] * v;
}

// ---------------- pass 4: out = x + mixed @ Wu + bu ------------------------------
__global__ void k_out(const float* __restrict__ x, const float* __restrict__ Wu,
                      const float* __restrict__ bu, float* __restrict__ out)
{
    __shared__ float4 sU[3][192];
    __shared__ float4 sB[192];
    int tid = threadIdx.x;
    float* sUf = (float*)sU;
    float* sBf = (float*)sB;
    for (int i = tid; i < DD * RR; i += 256) sUf[i] = Wu[i];  // Wu is (3,768) row-major
    for (int i = tid; i < DD; i += 256) sBf[i] = bu[i];
    __syncthreads();

    int warp = tid >> 5, lane = tid & 31;
    long long row = (long long)blockIdx.x * 8 + warp;
    int b = (int)(row >> 14), n = (int)(row & 16383);
    float m0 = g_mx[(b * 3 + 0) * NN + n];   // warp-uniform -> broadcast
    float m1 = g_mx[(b * 3 + 1) * NN + n];
    float m2 = g_mx[(b * 3 + 2) * NN + n];
    const float4* x4 = (const float4*)x + row * 192;
    float4* o4 = (float4*)out + row * 192;
#pragma unroll
    for (int i = 0; i < 6; i++) {
        int j = i * 32 + lane;
        float4 xv = x4[j];
        float4 u0 = sU[0][j], u1 = sU[1][j], u2 = sU[2][j], bv = sB[j];
        float4 o;
        o.x = fmaf(m2, u2.x, fmaf(m1, u1.x, fmaf(m0, u0.x, xv.x + bv.x)));
        o.y = fmaf(m2, u2.y, fmaf(m1, u1.y, fmaf(m0, u0.y, xv.y + bv.y)));
        o.z = fmaf(m2, u2.z, fmaf(m1, u1.z, fmaf(m0, u0.z, xv.z + bv.z)));
        o.w = fmaf(m2, u2.w, fmaf(m1, u1.w, fmaf(m0, u0.w, xv.w + bv.w)));
        o4[j] = o;
    }
}

// ---------------- launch ---------------------------------------------------------
extern "C" void kernel_launch(void* const* d_in, const int* in_sizes, int n_in,
                              void* d_out, int out_size)
{
    const float* x     = (const float*)d_in[0];
    const float* noise = (const float*)d_in[1];
    const float* Wd    = (const float*)d_in[2];
    const float* bd    = (const float*)d_in[3];
    const float* Wu    = (const float*)d_in[4];
    const float* bu    = (const float*)d_in[5];
    const float* Wg    = (const float*)d_in[6];
    const float* Wn    = (const float*)d_in[7];
    const float* dwk   = (const float*)d_in[8];
    const float* dwb   = (const float*)d_in[9];
    float* out = (float*)d_out;

    k_xr<<<16384, 256>>>(x, Wd, bd);
    k_gate<<<1, 256>>>(noise, Wg, Wn);
    k_conv1<<<(24 * HH * HH + 255) / 256, 256>>>(dwk, dwb);   // scale 1.0, writes g_mx

    const int sizes[3] = {64, 32, 16};
    for (int j = 1; j <= 3; j++) {
        int h = sizes[j - 1];
        int tot = 24 * h * h;
        k_down<<<(tot + 255) / 256, 256>>>(h, h);
        k_convs<<<(tot + 255) / 256, 256>>>(dwk, dwb, h, h);
        k_up<<<(24 * HH * HH + 255) / 256, 256>>>(h, h, j);
    }

    k_out<<<16384, 256>>>(x, Wu, bu, out);
}

// round 4
// speedup vs baseline: 1.0984x; 1.0984x over previous
#include <cuda_runtime.h>
#include <math.h>

#define BN   8
#define NN   16384
#define DD   768
#define RR   3
#define NEXP 4
#define HH   128

// ---------------- scratch (device globals; no allocation allowed) ----------------
__device__ float g_xr[BN * RR * NN];     // feat layout: [(b*3+r)*16384 + n], n = y*128+x
__device__ float g_mx[BN * RR * NN];     // mixed, same layout
__device__ float g_part[16384 * 3];      // per-block partial sums for the mean

// ---------------- pass 1: xr = x @ Wd + bd, + per-block partial sums -------------
__global__ void k_xr(const float* __restrict__ x, const float* __restrict__ Wd,
                     const float* __restrict__ bd)
{
    __shared__ float4 sW[3][192];     // Wd transposed: sW[r][e4]
    __shared__ float  sPart[8][3];
    int tid = threadIdx.x;
    float* sWf = (float*)sW;
    for (int i = tid; i < DD * RR; i += 256) {
        int r = i / DD, e = i % DD;
        sWf[r * DD + e] = Wd[e * RR + r];
    }
    __syncthreads();

    int warp = tid >> 5, lane = tid & 31;
    long long row = (long long)blockIdx.x * 8 + warp;   // (b*N + n)
    const float4* x4 = (const float4*)x + row * 192;

    float a0 = 0.f, a1 = 0.f, a2 = 0.f;
#pragma unroll
    for (int i = 0; i < 6; i++) {
        int j = i * 32 + lane;
        float4 xv = x4[j];
        float4 w0 = sW[0][j], w1 = sW[1][j], w2 = sW[2][j];
        a0 = fmaf(xv.x, w0.x, fmaf(xv.y, w0.y, fmaf(xv.z, w0.z, fmaf(xv.w, w0.w, a0))));
        a1 = fmaf(xv.x, w1.x, fmaf(xv.y, w1.y, fmaf(xv.z, w1.z, fmaf(xv.w, w1.w, a1))));
        a2 = fmaf(xv.x, w2.x, fmaf(xv.y, w2.y, fmaf(xv.z, w2.z, fmaf(xv.w, w2.w, a2))));
    }
#pragma unroll
    for (int o = 16; o; o >>= 1) {
        a0 += __shfl_down_sync(0xffffffffu, a0, o);
        a1 += __shfl_down_sync(0xffffffffu, a1, o);
        a2 += __shfl_down_sync(0xffffffffu, a2, o);
    }
    if (lane == 0) {
        int b = (int)(row >> 14);
        int n = (int)(row & 16383);
        a0 += bd[0]; a1 += bd[1]; a2 += bd[2];
        g_xr[(b * 3 + 0) * NN + n] = a0;
        g_xr[(b * 3 + 1) * NN + n] = a1;
        g_xr[(b * 3 + 2) * NN + n] = a2;
        sPart[warp][0] = a0; sPart[warp][1] = a1; sPart[warp][2] = a2;
    }
    __syncthreads();
    if (tid < 3) {
        float s = 0.f;
#pragma unroll
        for (int w = 0; w < 8; w++) s += sPart[w][tid];
        g_part[blockIdx.x * 3 + tid] = s;   // block's 8 rows all share one b
    }
}

// ---------------- helpers --------------------------------------------------------
__device__ __forceinline__ float bilin(const float* __restrict__ src, int ih, int iw,
                                       float sy, float sx)
{
    int y0 = (int)floorf(sy); float fy = sy - y0;
    int x0 = (int)floorf(sx); float fx = sx - x0;
    int y0c = min(max(y0, 0), ih - 1), y1c = min(max(y0 + 1, 0), ih - 1);
    int x0c = min(max(x0, 0), iw - 1), x1c = min(max(x0 + 1, 0), iw - 1);
    return (1.f - fy) * ((1.f - fx) * src[y0c * iw + x0c] + fx * src[y0c * iw + x1c])
         +        fy  * ((1.f - fx) * src[y1c * iw + x0c] + fx * src[y1c * iw + x1c]);
}

__device__ __forceinline__ float conv3x3(const float* __restrict__ src, int h, int w,
                                         int y, int xp, const float* __restrict__ k9,
                                         float bias)
{
    float acc = bias;
#pragma unroll
    for (int dy = -1; dy <= 1; dy++) {
        int yy = y + dy;
        if (yy < 0 || yy >= h) continue;
#pragma unroll
        for (int dx = -1; dx <= 1; dx++) {
            int xx = xp + dx;
            if (xx < 0 || xx >= w) continue;
            acc = fmaf(src[yy * w + xx], k9[(dy + 1) * 3 + (dx + 1)], acc);
        }
    }
    return acc;
}

// ---------------- fused pyramid: gating + all scales, one block per (b,r) plane --
__global__ void __launch_bounds__(512, 1)
k_pyr(const float* __restrict__ noise, const float* __restrict__ Wg,
      const float* __restrict__ Wn, const float* __restrict__ dwk,
      const float* __restrict__ dwb)
{
    __shared__ float sD64[64 * 64], sC64[64 * 64];
    __shared__ float sD32[32 * 32], sC32[32 * 32];
    __shared__ float sD16[16 * 16], sC16[16 * 16];
    __shared__ float sXa[3], sG[NEXP], sK[9], sBias[1];

    int p = blockIdx.x;            // 0..23
    int b = p / 3, r = p % 3;
    int tid = threadIdx.x;
    int warp = tid >> 5, lane = tid & 31;

    // --- gating: redundant per-block deterministic reduce over g_part (this b) ---
    if (warp < 3) {
        float s = 0.f;
        for (int k = lane; k < 2048; k += 32)
            s += g_part[(b * 2048 + k) * 3 + warp];
#pragma unroll
        for (int o = 16; o; o >>= 1) s += __shfl_down_sync(0xffffffffu, s, o);
        if (lane == 0) sXa[warp] = s * (1.0f / 16384.0f);
    }
    if (warp == 3) {
        if (lane < 9) sK[lane] = dwk[r * 9 + lane];
        if (lane == 9) sBias[0] = dwb[r];
    }
    __syncthreads();
    if (tid == 0) {
        float v[NEXP];
#pragma unroll
        for (int e = 0; e < NEXP; e++) {
            float hg = 0.f, hn = 0.f;
#pragma unroll
            for (int rr = 0; rr < RR; rr++) {
                hg = fmaf(sXa[rr], Wg[rr * NEXP + e], hg);
                hn = fmaf(sXa[rr], Wn[rr * NEXP + e], hn);
            }
            float sp = fmaxf(hn, 0.f) + log1pf(expf(-fabsf(hn)));  // stable softplus
            v[e] = hg + noise[b * NEXP + e] * sp;
        }
        int i1 = 0;
        for (int e = 1; e < NEXP; e++) if (v[e] > v[i1]) i1 = e;   // first-occurrence ties
        int i2 = -1;
        for (int e = 0; e < NEXP; e++) {
            if (e == i1) continue;
            if (i2 < 0 || v[e] > v[i2]) i2 = e;
        }
        float e2 = expf(v[i2] - v[i1]);
        float inv = 1.0f / (1.0f + e2);
#pragma unroll
        for (int e = 0; e < NEXP; e++) sG[e] = 0.f;
        sG[i1] = inv;
        sG[i2] = e2 * inv;
    }

    const float* __restrict__ plane = g_xr + p * NN;

    // --- downsample from full-res plane (L1/L2 resident) into smem ---
    for (int idx = tid; idx < 64 * 64; idx += 512) {
        int y = idx >> 6, xp = idx & 63;
        sD64[idx] = bilin(plane, HH, HH, (y + 0.5f) * 2.0f - 0.5f, (xp + 0.5f) * 2.0f - 0.5f);
    }
    for (int idx = tid; idx < 32 * 32; idx += 512) {
        int y = idx >> 5, xp = idx & 31;
        sD32[idx] = bilin(plane, HH, HH, (y + 0.5f) * 4.0f - 0.5f, (xp + 0.5f) * 4.0f - 0.5f);
    }
    for (int idx = tid; idx < 16 * 16; idx += 512) {
        int y = idx >> 4, xp = idx & 15;
        sD16[idx] = bilin(plane, HH, HH, (y + 0.5f) * 8.0f - 0.5f, (xp + 0.5f) * 8.0f - 0.5f);
    }
    __syncthreads();

    // --- depthwise conv at each downsampled resolution (zero pad) ---
    float bias = sBias[0];
    for (int idx = tid; idx < 64 * 64; idx += 512)
        sC64[idx] = conv3x3(sD64, 64, 64, idx >> 6, idx & 63, sK, bias);
    for (int idx = tid; idx < 32 * 32; idx += 512)
        sC32[idx] = conv3x3(sD32, 32, 32, idx >> 5, idx & 31, sK, bias);
    for (int idx = tid; idx < 16 * 16; idx += 512)
        sC16[idx] = conv3x3(sD16, 16, 16, idx >> 4, idx & 15, sK, bias);
    __syncthreads();

    // --- full-res conv + upsample all scales + gated accumulate -> g_mx ---
    float G0 = sG[0], G1 = sG[1], G2 = sG[2], G3 = sG[3];
    float* __restrict__ outp = g_mx + p * NN;
    for (int idx = tid; idx < NN; idx += 512) {
        int y = idx >> 7, xp = idx & 127;
        float cf = conv3x3(plane, HH, HH, y, xp, sK, bias);
        float u1 = bilin(sC64, 64, 64, (y + 0.5f) * 0.5f   - 0.5f, (xp + 0.5f) * 0.5f   - 0.5f);
        float u2 = bilin(sC32, 32, 32, (y + 0.5f) * 0.25f  - 0.5f, (xp + 0.5f) * 0.25f  - 0.5f);
        float u3 = bilin(sC16, 16, 16, (y + 0.5f) * 0.125f - 0.5f, (xp + 0.5f) * 0.125f - 0.5f);
        outp[idx] = fmaf(G0, cf, fmaf(G1, u1, fmaf(G2, u2, G3 * u3)));
    }
}

// ---------------- pass 4: out = x + mixed @ Wu + bu ------------------------------
__global__ void k_out(const float* __restrict__ x, const float* __restrict__ Wu,
                      const float* __restrict__ bu, float* __restrict__ out)
{
    __shared__ float4 sU[3][192];
    __shared__ float4 sB[192];
    int tid = threadIdx.x;
    float* sUf = (float*)sU;
    float* sBf = (float*)sB;
    for (int i = tid; i < DD * RR; i += 256) sUf[i] = Wu[i];  // Wu is (3,768) row-major
    for (int i = tid; i < DD; i += 256) sBf[i] = bu[i];
    __syncthreads();

    int warp = tid >> 5, lane = tid & 31;
    long long row = (long long)blockIdx.x * 8 + warp;
    int b = (int)(row >> 14), n = (int)(row & 16383);
    float m0 = g_mx[(b * 3 + 0) * NN + n];   // warp-uniform -> broadcast
    float m1 = g_mx[(b * 3 + 1) * NN + n];
    float m2 = g_mx[(b * 3 + 2) * NN + n];
    const float4* x4 = (const float4*)x + row * 192;
    float4* o4 = (float4*)out + row * 192;
#pragma unroll
    for (int i = 0; i < 6; i++) {
        int j = i * 32 + lane;
        float4 xv = x4[j];
        float4 u0 = sU[0][j], u1 = sU[1][j], u2 = sU[2][j], bv = sB[j];
        float4 o;
        o.x = fmaf(m2, u2.x, fmaf(m1, u1.x, fmaf(m0, u0.x, xv.x + bv.x)));
        o.y = fmaf(m2, u2.y, fmaf(m1, u1.y, fmaf(m0, u0.y, xv.y + bv.y)));
        o.z = fmaf(m2, u2.z, fmaf(m1, u1.z, fmaf(m0, u0.z, xv.z + bv.z)));
        o.w = fmaf(m2, u2.w, fmaf(m1, u1.w, fmaf(m0, u0.w, xv.w + bv.w)));
        o4[j] = o;
    }
}

// ---------------- launch ---------------------------------------------------------
extern "C" void kernel_launch(void* const* d_in, const int* in_sizes, int n_in,
                              void* d_out, int out_size)
{
    const float* x     = (const float*)d_in[0];
    const float* noise = (const float*)d_in[1];
    const float* Wd    = (const float*)d_in[2];
    const float* bd    = (const float*)d_in[3];
    const float* Wu    = (const float*)d_in[4];
    const float* bu    = (const float*)d_in[5];
    const float* Wg    = (const float*)d_in[6];
    const float* Wn    = (const float*)d_in[7];
    const float* dwk   = (const float*)d_in[8];
    const float* dwb   = (const float*)d_in[9];
    float* out = (float*)d_out;

    k_xr<<<16384, 256>>>(x, Wd, bd);
    k_pyr<<<24, 512>>>(noise, Wg, Wn, dwk, dwb);
    k_out<<<16384, 256>>>(x, Wu, bu, out);
}